// round 13
// baseline (speedup 1.0000x reference)
#include <cuda_runtime.h>
#include <cuda_fp16.h>
#include <cstdint>

// ---------------------------------------------------------------------------
// y[m, o] = (sum_k x[m,k] * w_q[o,k]) * 2^s_exp[o] + bias[o]
// M = 16384, N = 2048, K = 2048.
// Launch 1: fused prep(scale/bias) + x fp32->fp16 + w->fp16 (MLP=4).
// Launch 2: HMMA GEMM, BM=128 BN=256 BK=64, 4 stages, 2 chunks/round
//           (R12-proven), now with 64x64 WARP TILES (8 warps, 256 threads):
//           -33% smem bytes/FLOP (R12 ncu: L1 60.1% co-binding with tensor
//           71.3%) + register double-buffered fragments (255-reg budget at
//           256 thr makes the R11 idea actually fit).
// ---------------------------------------------------------------------------

static constexpr int M_TOTAL = 16384;
static constexpr int N_TOTAL = 2048;
static constexpr int K_TOTAL = 2048;

static constexpr int BM = 128;
static constexpr int BN = 256;
static constexpr int BK = 64;                 // 64 halves = 128 B per row
static constexpr int KITERS = K_TOTAL / BK;   // 32 chunks, 16 rounds
static constexpr int STAGES = 4;
static constexpr int THREADS = 256;           // 8 warps: 2 (m) x 4 (n), tile 64x64

static constexpr uint32_t A_STAGE_BYTES = BM * 128;           // 16384
static constexpr uint32_t B_STAGE_BYTES = BN * 128;           // 32768
static constexpr uint32_t STAGE_BYTES   = A_STAGE_BYTES + B_STAGE_BYTES; // 49152
static constexpr uint32_t SMEM_TOTAL    = STAGES * STAGE_BYTES;          // 196608

// scratch
__device__ __half g_x16[(size_t)M_TOTAL * K_TOTAL];   // 64 MB
__device__ __half g_w16[(size_t)N_TOTAL * K_TOTAL];   // 8 MB
__device__ float  g_scale[N_TOTAL];
__device__ float  g_bias[N_TOTAL];

// ---------------------------------------------------------------------------
// helpers
// ---------------------------------------------------------------------------
__device__ __forceinline__ uint32_t smem_to_u32(const void* p) {
    uint32_t a;
    asm("{ .reg .u64 t; cvta.to.shared.u64 t, %1; cvt.u32.u64 %0, t; }"
        : "=r"(a) : "l"(p));
    return a;
}

__device__ __forceinline__ void cp_async_16(uint32_t saddr, const void* gptr) {
    asm volatile("cp.async.cg.shared.global [%0], [%1], 16;"
                 :: "r"(saddr), "l"(gptr) : "memory");
}
__device__ __forceinline__ void cp_async_commit() {
    asm volatile("cp.async.commit_group;" ::: "memory");
}
template <int N>
__device__ __forceinline__ void cp_async_wait() {
    asm volatile("cp.async.wait_group %0;" :: "n"(N) : "memory");
}

__device__ __forceinline__ void ldsm_x4(uint32_t& r0, uint32_t& r1,
                                        uint32_t& r2, uint32_t& r3, uint32_t addr) {
    asm volatile("ldmatrix.sync.aligned.m8n8.x4.shared.b16 {%0,%1,%2,%3}, [%4];"
                 : "=r"(r0), "=r"(r1), "=r"(r2), "=r"(r3) : "r"(addr));
}

__device__ __forceinline__ void mma_16816(float* c, const uint32_t* a, const uint32_t* b) {
    asm volatile(
        "mma.sync.aligned.m16n8k16.row.col.f32.f16.f16.f32 "
        "{%0,%1,%2,%3}, {%4,%5,%6,%7}, {%8,%9}, {%0,%1,%2,%3};"
        : "+f"(c[0]), "+f"(c[1]), "+f"(c[2]), "+f"(c[3])
        : "r"(a[0]), "r"(a[1]), "r"(a[2]), "r"(a[3]), "r"(b[0]), "r"(b[1]));
}

// per-128B-row XOR swizzle: physical 16B-chunk = chunk ^ (row & 7)
__device__ __forceinline__ uint32_t sw_off(int row, int chunk) {
    return (uint32_t)(row * 128 + ((chunk ^ (row & 7)) << 4));
}

// ---------------------------------------------------------------------------
// dtype / binding detection
// ---------------------------------------------------------------------------
__device__ __forceinline__ int looks_se_bytes(const unsigned char* p) {
    int ok = 1;
#pragma unroll 8
    for (int i = 0; i < 64; ++i) {
        unsigned char b = p[i];
        if (!(b == 0x00 || b >= 0xF8)) ok = 0;
    }
    return ok;
}
__device__ __forceinline__ int looks_i32_groups(const unsigned char* p, int groups,
                                                unsigned char lo_min) {
    int ok = 1;
#pragma unroll 4
    for (int j = 0; j < groups; ++j) {
        unsigned char b0 = p[4 * j], b1 = p[4 * j + 1],
                      b2 = p[4 * j + 2], b3 = p[4 * j + 3];
        unsigned char ext = (b0 >= lo_min) ? 0xFF : 0x00;
        int b0ok = (b0 == 0x00) || (b0 == 0x01 && lo_min == 0xFF) || (b0 >= lo_min);
        if (!(b0ok && b1 == ext && b2 == ext && b3 == ext)) ok = 0;
    }
    return ok;
}

// ---------------------------------------------------------------------------
// Launch 1: fused prep + converts (identical to the R10/R12 version)
// ---------------------------------------------------------------------------
static constexpr int XBLK = M_TOTAL * K_TOTAL / 8192;   // 4096
static constexpr int WBLK = N_TOTAL * K_TOTAL / 4096;   // 1024

__global__ void __launch_bounds__(256)
prep_cvt_kernel(const float* __restrict__ x, const void* __restrict__ wq,
                const void* __restrict__ c0, const void* __restrict__ c1) {
    const int b = blockIdx.x;
    const int tid = threadIdx.x;
    if (b == 0) {
        const int c0_is_se = looks_se_bytes((const unsigned char*)c0);
        const void*  sep = c0_is_se ? c0 : c1;
        const float* bi  = (const float*)(c0_is_se ? c1 : c0);
        const int se32 = looks_i32_groups((const unsigned char*)sep, 64, 0xF8);
#pragma unroll
        for (int t = 0; t < 8; ++t) {
            const int i = tid + t * 256;
            const int e = se32 ? ((const int*)sep)[i]
                               : (int)((const signed char*)sep)[i];
            g_scale[i] = __int_as_float((127 + e) << 23);   // exact 2^s_exp
            g_bias[i]  = bi[i];
        }
    } else if (b <= XBLK) {
        const size_t slot0 = (size_t)(b - 1) * 2048;
        const float4* xi = reinterpret_cast<const float4*>(x) + slot0;
        uint2*        xo = reinterpret_cast<uint2*>(g_x16) + slot0;
#pragma unroll
        for (int batch = 0; batch < 2; ++batch) {
            float4 v[4];
#pragma unroll
            for (int t = 0; t < 4; ++t)
                v[t] = __ldcs(xi + tid + (batch * 4 + t) * 256);
#pragma unroll
            for (int t = 0; t < 4; ++t) {
                __half2 a = __floats2half2_rn(v[t].x, v[t].y);
                __half2 c = __floats2half2_rn(v[t].z, v[t].w);
                uint2 o;
                o.x = *reinterpret_cast<const uint32_t*>(&a);
                o.y = *reinterpret_cast<const uint32_t*>(&c);
                xo[tid + (batch * 4 + t) * 256] = o;
            }
        }
    } else {
        const int w_is32 = looks_i32_groups((const unsigned char*)wq, 64, 0xFF);
        const size_t e0 = (size_t)(b - 1 - XBLK) * 4096;
        if (w_is32) {
            const int4* wi = reinterpret_cast<const int4*>((const int*)wq + e0);
            int4 v[4];
#pragma unroll
            for (int t = 0; t < 4; ++t)
                v[t] = __ldcs(wi + tid + t * 256);
#pragma unroll
            for (int t = 0; t < 4; ++t) {
                const int slot = tid + t * 256;
                uint32_t u0 = (((uint32_t)v[t].x >> 16) & 0x8000u)
                            | ((uint32_t)(v[t].x & 1) * 0x3C00u);
                uint32_t u1 = (((uint32_t)v[t].y >> 16) & 0x8000u)
                            | ((uint32_t)(v[t].y & 1) * 0x3C00u);
                uint32_t u2 = (((uint32_t)v[t].z >> 16) & 0x8000u)
                            | ((uint32_t)(v[t].z & 1) * 0x3C00u);
                uint32_t u3 = (((uint32_t)v[t].w >> 16) & 0x8000u)
                            | ((uint32_t)(v[t].w & 1) * 0x3C00u);
                uint2 o; o.x = u0 | (u1 << 16); o.y = u2 | (u3 << 16);
                reinterpret_cast<uint2*>(g_w16 + e0)[slot] = o;
            }
        } else {
#pragma unroll
            for (int t = 0; t < 2; ++t) {
                const int slot = tid + t * 256;
                unsigned long long v = reinterpret_cast<const unsigned long long*>(
                    (const signed char*)wq + e0)[slot];
                uint32_t h2[4];
#pragma unroll
                for (int j = 0; j < 4; ++j) {
                    int b0 = (int)(signed char)(v >> (16 * j));
                    int b1 = (int)(signed char)(v >> (16 * j + 8));
                    uint32_t u0 = ((uint32_t)(b0 << 8) & 0x8000u) | ((uint32_t)(b0 & 1) * 0x3C00u);
                    uint32_t u1 = ((uint32_t)(b1 << 8) & 0x8000u) | ((uint32_t)(b1 & 1) * 0x3C00u);
                    h2[j] = u0 | (u1 << 16);
                }
                uint4 q; q.x = h2[0]; q.y = h2[1]; q.z = h2[2]; q.w = h2[3];
                reinterpret_cast<uint4*>(g_w16 + e0)[slot] = q;
            }
        }
    }
}

// ---------------------------------------------------------------------------
// Launch 2: GEMM. grid = (8, 128), 256 threads, 8 warps (2m x 4n), tile 64x64.
// 4 stages, 2 chunks per round; fragments double-buffered in registers with
// ks+1 prefetch ahead of ks MMAs (8 ks per round spanning two stages).
// ---------------------------------------------------------------------------
__global__ void __launch_bounds__(THREADS)
bitlinear_gemm_kernel(float* __restrict__ out) {
    extern __shared__ __align__(1024) char smem[];
    const uint32_t smem_base = smem_to_u32(smem);

    const int tid  = threadIdx.x;
    const int warp = tid >> 5;
    const int lane = tid & 31;
    const int wm   = warp >> 2;      // 0..1
    const int wn   = warp & 3;       // 0..3

    const int n0 = blockIdx.x * BN;
    const int m0 = blockIdx.y * BM;

    const __half* gA = g_x16 + (size_t)m0 * K_TOTAL;
    const __half* gW = g_w16 + (size_t)n0 * K_TOTAL;

    auto issue_stage = [&](int c) {
        const uint32_t sa = smem_base + (uint32_t)(c & 3) * STAGE_BYTES;
        const uint32_t sb = sa + A_STAGE_BYTES;
        const int kb = c * BK;
#pragma unroll
        for (int t = 0; t < 4; ++t) {                 // A: 1024 chunks
            int idx = tid + t * THREADS;
            int r = idx >> 3, ch = idx & 7;
            cp_async_16(sa + sw_off(r, ch), gA + (size_t)r * K_TOTAL + kb + ch * 8);
        }
#pragma unroll
        for (int t = 0; t < 8; ++t) {                 // B: 2048 chunks
            int idx = tid + t * THREADS;
            int r = idx >> 3, ch = idx & 7;
            cp_async_16(sb + sw_off(r, ch), gW + (size_t)r * K_TOTAL + kb + ch * 8);
        }
    };

    // prologue: chunks 0,1 in one commit group
    issue_stage(0); issue_stage(1); cp_async_commit();

    float acc[4][8][4];
#pragma unroll
    for (int i = 0; i < 4; ++i)
#pragma unroll
        for (int j = 0; j < 8; ++j)
#pragma unroll
            for (int k = 0; k < 4; ++k) acc[i][j][k] = 0.f;

    const int a_row_in = (lane & 7) + ((lane >> 3) & 1) * 8;
    const int a_chpar  = lane >> 4;
    const int b_row_in = ((lane >> 4) << 3) + (lane & 7);
    const int b_chpar  = (lane >> 3) & 1;

    uint32_t af[2][4][4];      // [buf][mtile][regs]
    uint32_t bf[2][8][2];      // [buf][ntile][regs]

    // load fragments for ks-step `ks` (0..3) from stage bases (sa, sb) into buf
    auto load_frags = [&](uint32_t sa, uint32_t sb, int ks, int buf) {
#pragma unroll
        for (int i = 0; i < 4; ++i) {
            int m = wm * 64 + i * 16 + a_row_in;
            ldsm_x4(af[buf][i][0], af[buf][i][1], af[buf][i][2], af[buf][i][3],
                    sa + sw_off(m, ks * 2 + a_chpar));
        }
#pragma unroll
        for (int p = 0; p < 4; ++p) {
            int n = wn * 64 + p * 16 + b_row_in;
            uint32_t r0, r1, r2, r3;
            ldsm_x4(r0, r1, r2, r3, sb + sw_off(n, ks * 2 + b_chpar));
            bf[buf][2 * p][0] = r0;     bf[buf][2 * p][1] = r1;
            bf[buf][2 * p + 1][0] = r2; bf[buf][2 * p + 1][1] = r3;
        }
    };

#pragma unroll 1
    for (int c = 0; c < KITERS; c += 2) {
        cp_async_wait<0>();              // chunks c, c+1 resident
        __syncthreads();                 // all warps done with the 2 stages
                                         // we are about to overwrite
        if (c + 2 < KITERS) {
            issue_stage(c + 2);
            issue_stage(c + 3);
            cp_async_commit();
        }
        const uint32_t s0 = smem_base + (uint32_t)(c & 3) * STAGE_BYTES;
        const uint32_t s1 = smem_base + (uint32_t)((c + 1) & 3) * STAGE_BYTES;

        load_frags(s0, s0 + A_STAGE_BYTES, 0, 0);   // prime ks=0
#pragma unroll
        for (int ks = 0; ks < 8; ++ks) {
            const int cur = ks & 1;
            if (ks < 7) {
                const int nk = ks + 1;
                const uint32_t sa = (nk < 4) ? s0 : s1;
                load_frags(sa, sa + A_STAGE_BYTES, nk & 3, cur ^ 1);
            }
#pragma unroll
            for (int i = 0; i < 4; ++i)
#pragma unroll
                for (int j = 0; j < 8; ++j)
                    mma_16816(acc[i][j], af[cur][i], bf[cur][j]);
        }
    }

    // epilogue: y * 2^s_exp + bias; streaming stores
    const int col_lo = 2 * (lane & 3);
    const int row_lo = lane >> 2;
#pragma unroll
    for (int j = 0; j < 8; ++j) {
        const int nc = n0 + wn * 64 + j * 8 + col_lo;
        const float s0 = g_scale[nc], s1 = g_scale[nc + 1];
        const float b0 = g_bias[nc],  b1 = g_bias[nc + 1];
#pragma unroll
        for (int i = 0; i < 4; ++i) {
            const int mr = m0 + wm * 64 + i * 16 + row_lo;
            float2 v0, v1;
            v0.x = acc[i][j][0] * s0 + b0;  v0.y = acc[i][j][1] * s1 + b1;
            v1.x = acc[i][j][2] * s0 + b0;  v1.y = acc[i][j][3] * s1 + b1;
            __stcs(reinterpret_cast<float2*>(out + (size_t)mr * N_TOTAL + nc), v0);
            __stcs(reinterpret_cast<float2*>(out + (size_t)(mr + 8) * N_TOTAL + nc), v1);
        }
    }
}

// ---------------------------------------------------------------------------
// host launcher — bind by element count; 2 launches per call
// ---------------------------------------------------------------------------
extern "C" void kernel_launch(void* const* d_in, const int* in_sizes, int n_in,
                              void* d_out, int out_size) {
    const void* x_p  = nullptr;
    const void* w_p  = nullptr;
    const void* c0_p = nullptr;
    const void* c1_p = nullptr;
    for (int i = 0; i < n_in; ++i) {
        if      (in_sizes[i] == M_TOTAL * K_TOTAL) x_p = d_in[i];
        else if (in_sizes[i] == N_TOTAL * K_TOTAL) w_p = d_in[i];
        else if (!c0_p)                            c0_p = d_in[i];
        else                                       c1_p = d_in[i];
    }
    float* out = (float*)d_out;

    static bool attr_set = false;
    if (!attr_set) {
        cudaFuncSetAttribute(bitlinear_gemm_kernel,
                             cudaFuncAttributeMaxDynamicSharedMemorySize, SMEM_TOTAL);
        attr_set = true;
    }

    prep_cvt_kernel<<<1 + XBLK + WBLK, 256>>>((const float*)x_p, w_p, c0_p, c1_p);

    dim3 grid(N_TOTAL / BN, M_TOTAL / BM);   // (8, 128), n fastest
    bitlinear_gemm_kernel<<<grid, THREADS, SMEM_TOTAL>>>(out);
}

// round 15
// speedup vs baseline: 1.0693x; 1.0693x over previous
#include <cuda_runtime.h>
#include <cuda_fp16.h>
#include <cstdint>

// ---------------------------------------------------------------------------
// y[m, o] = (sum_k x[m,k] * w_q[o,k]) * 2^s_exp[o] + bias[o]
// M = 16384, N = 2048, K = 2048.
// Launch 1: fused prep(scale/bias) + x fp32->fp16 + w->fp16 (MLP=4, 512 thr).
// Launch 2: R12-proven HMMA GEMM (BM=128 BN=256 BK=64, 4 stages, 2 chunks
//           per sync round, 16 warps, warp tile 32x64) with POST-barrier
//           ks=0 fragment prefetch (R14's pre-barrier variant was unsound:
//           cp.async.wait_group is per-thread; cross-thread visibility of
//           copied tiles requires the barrier) and smem-staged epilogue
//           constants (published by the round-0 barrier).
// ---------------------------------------------------------------------------

static constexpr int M_TOTAL = 16384;
static constexpr int N_TOTAL = 2048;
static constexpr int K_TOTAL = 2048;

static constexpr int BM = 128;
static constexpr int BN = 256;
static constexpr int BK = 64;                 // 64 halves = 128 B per row
static constexpr int KITERS = K_TOTAL / BK;   // 32 chunks, 16 rounds
static constexpr int STAGES = 4;
static constexpr int THREADS = 512;           // 16 warps: 4 (m) x 4 (n)

static constexpr uint32_t A_STAGE_BYTES = BM * 128;           // 16384
static constexpr uint32_t B_STAGE_BYTES = BN * 128;           // 32768
static constexpr uint32_t STAGE_BYTES   = A_STAGE_BYTES + B_STAGE_BYTES; // 49152
static constexpr uint32_t EPI_BYTES     = 2048;               // 256 scale + 256 bias
static constexpr uint32_t SMEM_TOTAL    = STAGES * STAGE_BYTES + EPI_BYTES; // 198656

// scratch
__device__ __half g_x16[(size_t)M_TOTAL * K_TOTAL];   // 64 MB
__device__ __half g_w16[(size_t)N_TOTAL * K_TOTAL];   // 8 MB
__device__ float  g_scale[N_TOTAL];
__device__ float  g_bias[N_TOTAL];

// ---------------------------------------------------------------------------
// helpers
// ---------------------------------------------------------------------------
__device__ __forceinline__ uint32_t smem_to_u32(const void* p) {
    uint32_t a;
    asm("{ .reg .u64 t; cvta.to.shared.u64 t, %1; cvt.u32.u64 %0, t; }"
        : "=r"(a) : "l"(p));
    return a;
}

__device__ __forceinline__ void cp_async_16(uint32_t saddr, const void* gptr) {
    asm volatile("cp.async.cg.shared.global [%0], [%1], 16;"
                 :: "r"(saddr), "l"(gptr) : "memory");
}
__device__ __forceinline__ void cp_async_commit() {
    asm volatile("cp.async.commit_group;" ::: "memory");
}
template <int N>
__device__ __forceinline__ void cp_async_wait() {
    asm volatile("cp.async.wait_group %0;" :: "n"(N) : "memory");
}

__device__ __forceinline__ void ldsm_x4(uint32_t& r0, uint32_t& r1,
                                        uint32_t& r2, uint32_t& r3, uint32_t addr) {
    asm volatile("ldmatrix.sync.aligned.m8n8.x4.shared.b16 {%0,%1,%2,%3}, [%4];"
                 : "=r"(r0), "=r"(r1), "=r"(r2), "=r"(r3) : "r"(addr));
}

__device__ __forceinline__ void mma_16816(float* c, const uint32_t* a, const uint32_t* b) {
    asm volatile(
        "mma.sync.aligned.m16n8k16.row.col.f32.f16.f16.f32 "
        "{%0,%1,%2,%3}, {%4,%5,%6,%7}, {%8,%9}, {%0,%1,%2,%3};"
        : "+f"(c[0]), "+f"(c[1]), "+f"(c[2]), "+f"(c[3])
        : "r"(a[0]), "r"(a[1]), "r"(a[2]), "r"(a[3]), "r"(b[0]), "r"(b[1]));
}

// per-128B-row XOR swizzle: physical 16B-chunk = chunk ^ (row & 7)
__device__ __forceinline__ uint32_t sw_off(int row, int chunk) {
    return (uint32_t)(row * 128 + ((chunk ^ (row & 7)) << 4));
}

// ---------------------------------------------------------------------------
// dtype / binding detection
// ---------------------------------------------------------------------------
__device__ __forceinline__ int looks_se_bytes(const unsigned char* p) {
    int ok = 1;
#pragma unroll 8
    for (int i = 0; i < 64; ++i) {
        unsigned char b = p[i];
        if (!(b == 0x00 || b >= 0xF8)) ok = 0;
    }
    return ok;
}
__device__ __forceinline__ int looks_i32_groups(const unsigned char* p, int groups,
                                                unsigned char lo_min) {
    int ok = 1;
#pragma unroll 4
    for (int j = 0; j < groups; ++j) {
        unsigned char b0 = p[4 * j], b1 = p[4 * j + 1],
                      b2 = p[4 * j + 2], b3 = p[4 * j + 3];
        unsigned char ext = (b0 >= lo_min) ? 0xFF : 0x00;
        int b0ok = (b0 == 0x00) || (b0 == 0x01 && lo_min == 0xFF) || (b0 >= lo_min);
        if (!(b0ok && b1 == ext && b2 == ext && b3 == ext)) ok = 0;
    }
    return ok;
}

// ---------------------------------------------------------------------------
// Launch 1: fused prep + converts (512-thread blocks)
// ---------------------------------------------------------------------------
static constexpr int XBLK = M_TOTAL * K_TOTAL / 16384;  // 2048 (4096 float4/blk)
static constexpr int WBLK = N_TOTAL * K_TOTAL / 8192;   // 512  (8192 w/blk)

__global__ void __launch_bounds__(512)
prep_cvt_kernel(const float* __restrict__ x, const void* __restrict__ wq,
                const void* __restrict__ c0, const void* __restrict__ c1) {
    const int b = blockIdx.x;
    const int tid = threadIdx.x;
    if (b == 0) {
        const int c0_is_se = looks_se_bytes((const unsigned char*)c0);
        const void*  sep = c0_is_se ? c0 : c1;
        const float* bi  = (const float*)(c0_is_se ? c1 : c0);
        const int se32 = looks_i32_groups((const unsigned char*)sep, 64, 0xF8);
#pragma unroll
        for (int t = 0; t < 4; ++t) {
            const int i = tid + t * 512;
            const int e = se32 ? ((const int*)sep)[i]
                               : (int)((const signed char*)sep)[i];
            g_scale[i] = __int_as_float((127 + e) << 23);   // exact 2^s_exp
            g_bias[i]  = bi[i];
        }
    } else if (b <= XBLK) {
        // block owns 4096 float4 slots; thread does slots tid+t*512, t=0..7
        const size_t slot0 = (size_t)(b - 1) * 4096;
        const float4* xi = reinterpret_cast<const float4*>(x) + slot0;
        uint2*        xo = reinterpret_cast<uint2*>(g_x16) + slot0;
#pragma unroll
        for (int batch = 0; batch < 2; ++batch) {
            float4 v[4];
#pragma unroll
            for (int t = 0; t < 4; ++t)                     // MLP=4
                v[t] = __ldcs(xi + tid + (batch * 4 + t) * 512);
#pragma unroll
            for (int t = 0; t < 4; ++t) {
                __half2 a = __floats2half2_rn(v[t].x, v[t].y);
                __half2 c = __floats2half2_rn(v[t].z, v[t].w);
                uint2 o;
                o.x = *reinterpret_cast<const uint32_t*>(&a);
                o.y = *reinterpret_cast<const uint32_t*>(&c);
                xo[tid + (batch * 4 + t) * 512] = o;
            }
        }
    } else {
        const int w_is32 = looks_i32_groups((const unsigned char*)wq, 64, 0xFF);
        const size_t e0 = (size_t)(b - 1 - XBLK) * 8192;    // element base
        if (w_is32) {
            // 2048 int4 slots per block; thread does slots tid+t*512, t=0..3
            const int4* wi = reinterpret_cast<const int4*>((const int*)wq + e0);
            int4 v[4];
#pragma unroll
            for (int t = 0; t < 4; ++t)                     // MLP=4
                v[t] = __ldcs(wi + tid + t * 512);
#pragma unroll
            for (int t = 0; t < 4; ++t) {
                const int slot = tid + t * 512;
                uint32_t u0 = (((uint32_t)v[t].x >> 16) & 0x8000u)
                            | ((uint32_t)(v[t].x & 1) * 0x3C00u);
                uint32_t u1 = (((uint32_t)v[t].y >> 16) & 0x8000u)
                            | ((uint32_t)(v[t].y & 1) * 0x3C00u);
                uint32_t u2 = (((uint32_t)v[t].z >> 16) & 0x8000u)
                            | ((uint32_t)(v[t].z & 1) * 0x3C00u);
                uint32_t u3 = (((uint32_t)v[t].w >> 16) & 0x8000u)
                            | ((uint32_t)(v[t].w & 1) * 0x3C00u);
                uint2 o; o.x = u0 | (u1 << 16); o.y = u2 | (u3 << 16);
                reinterpret_cast<uint2*>(g_w16 + e0)[slot] = o;
            }
        } else {
            // int8: 1024 u64 slots per block; thread does slots tid+t*512
#pragma unroll
            for (int t = 0; t < 2; ++t) {
                const int slot = tid + t * 512;
                unsigned long long v = reinterpret_cast<const unsigned long long*>(
                    (const signed char*)wq + e0)[slot];
                uint32_t h2[4];
#pragma unroll
                for (int j = 0; j < 4; ++j) {
                    int b0 = (int)(signed char)(v >> (16 * j));
                    int b1 = (int)(signed char)(v >> (16 * j + 8));
                    uint32_t u0 = ((uint32_t)(b0 << 8) & 0x8000u) | ((uint32_t)(b0 & 1) * 0x3C00u);
                    uint32_t u1 = ((uint32_t)(b1 << 8) & 0x8000u) | ((uint32_t)(b1 & 1) * 0x3C00u);
                    h2[j] = u0 | (u1 << 16);
                }
                uint4 q; q.x = h2[0]; q.y = h2[1]; q.z = h2[2]; q.w = h2[3];
                reinterpret_cast<uint4*>(g_w16 + e0)[slot] = q;
            }
        }
    }
}

// ---------------------------------------------------------------------------
// Launch 2: GEMM. grid = (8, 128), 512 threads, warp (4m x 4n), tile 32x64.
// 4 stages, 2 chunks/round. ALL smem reads occur after wait<0> + barrier.
// ks=0 fragments of each stage prefetched (post-barrier) ahead of the MMA
// block so the warm-up ldsm latency overlaps the previous stage's MMAs.
// ---------------------------------------------------------------------------
__global__ void __launch_bounds__(THREADS, 1)
bitlinear_gemm_kernel(float* __restrict__ out) {
    extern __shared__ __align__(1024) char smem[];
    const uint32_t smem_base = smem_to_u32(smem);

    const int tid  = threadIdx.x;
    const int warp = tid >> 5;
    const int lane = tid & 31;
    const int wm   = warp >> 2;      // 0..3
    const int wn   = warp & 3;       // 0..3

    const int n0 = blockIdx.x * BN;
    const int m0 = blockIdx.y * BM;

    const __half* gA = g_x16 + (size_t)m0 * K_TOTAL;
    const __half* gW = g_w16 + (size_t)n0 * K_TOTAL;

    auto issue_stage = [&](int c) {
        const uint32_t sa = smem_base + (uint32_t)(c & 3) * STAGE_BYTES;
        const uint32_t sb = sa + A_STAGE_BYTES;
        const int kb = c * BK;
#pragma unroll
        for (int t = 0; t < 2; ++t) {                 // A: 1024 chunks
            int idx = tid + t * THREADS;
            int r = idx >> 3, ch = idx & 7;
            cp_async_16(sa + sw_off(r, ch), gA + (size_t)r * K_TOTAL + kb + ch * 8);
        }
#pragma unroll
        for (int t = 0; t < 4; ++t) {                 // B: 2048 chunks
            int idx = tid + t * THREADS;
            int r = idx >> 3, ch = idx & 7;
            cp_async_16(sb + sw_off(r, ch), gW + (size_t)r * K_TOTAL + kb + ch * 8);
        }
    };

    // prologue: chunks 0,1 in one commit group; stage epilogue constants.
    // The smem epilogue writes are published to all threads by the first
    // round's __syncthreads (reads happen only after the loop).
    issue_stage(0); issue_stage(1); cp_async_commit();
    {
        float* ep = reinterpret_cast<float*>(smem + STAGES * STAGE_BYTES);
        if (tid < 256) ep[tid]               = g_scale[n0 + tid];
        else           ep[256 + (tid - 256)] = g_bias[n0 + (tid - 256)];
    }

    float acc[2][8][4];
#pragma unroll
    for (int i = 0; i < 2; ++i)
#pragma unroll
        for (int j = 0; j < 8; ++j)
#pragma unroll
            for (int k = 0; k < 4; ++k) acc[i][j][k] = 0.f;

    const int a_row_in = (lane & 7) + ((lane >> 3) & 1) * 8;
    const int a_chpar  = lane >> 4;
    const int b_row_in = ((lane >> 4) << 3) + (lane & 7);
    const int b_chpar  = (lane >> 3) & 1;

    uint32_t af0[2][4];   // prefetched ks=0 fragments
    uint32_t bf0[8][2];

    auto load_frags0 = [&](uint32_t sa, uint32_t sb) {
#pragma unroll
        for (int i = 0; i < 2; ++i) {
            int m = wm * 32 + i * 16 + a_row_in;
            ldsm_x4(af0[i][0], af0[i][1], af0[i][2], af0[i][3],
                    sa + sw_off(m, a_chpar));
        }
#pragma unroll
        for (int p = 0; p < 4; ++p) {
            int n = wn * 64 + p * 16 + b_row_in;
            uint32_t r0, r1, r2, r3;
            ldsm_x4(r0, r1, r2, r3, sb + sw_off(n, b_chpar));
            bf0[2 * p][0] = r0;     bf0[2 * p][1] = r1;
            bf0[2 * p + 1][0] = r2; bf0[2 * p + 1][1] = r3;
        }
    };

    // compute one stage; ks0 uses the prefetched frags, ks1..3 load inline
    auto compute_stage = [&](uint32_t sa, uint32_t sb) {
#pragma unroll
        for (int i = 0; i < 2; ++i)
#pragma unroll
            for (int j = 0; j < 8; ++j)
                mma_16816(acc[i][j], af0[i], bf0[j]);
#pragma unroll
        for (int ks = 1; ks < 4; ++ks) {
            uint32_t af[2][4];
#pragma unroll
            for (int i = 0; i < 2; ++i) {
                int m = wm * 32 + i * 16 + a_row_in;
                ldsm_x4(af[i][0], af[i][1], af[i][2], af[i][3],
                        sa + sw_off(m, ks * 2 + a_chpar));
            }
            uint32_t bf[8][2];
#pragma unroll
            for (int p = 0; p < 4; ++p) {
                int n = wn * 64 + p * 16 + b_row_in;
                uint32_t r0, r1, r2, r3;
                ldsm_x4(r0, r1, r2, r3, sb + sw_off(n, ks * 2 + b_chpar));
                bf[2 * p][0] = r0;     bf[2 * p][1] = r1;
                bf[2 * p + 1][0] = r2; bf[2 * p + 1][1] = r3;
            }
#pragma unroll
            for (int i = 0; i < 2; ++i)
#pragma unroll
                for (int j = 0; j < 8; ++j)
                    mma_16816(acc[i][j], af[i], bf[j]);
        }
    };

#pragma unroll 1
    for (int c = 0; c < KITERS; c += 2) {
        cp_async_wait<0>();              // this thread's chunks c, c+1 done
        __syncthreads();                 // publishes ALL threads' copies; also
                                         // protects stages about to be refilled
        if (c + 2 < KITERS) {
            issue_stage(c + 2);
            issue_stage(c + 3);
            cp_async_commit();
        }
        const uint32_t s0 = smem_base + (uint32_t)(c & 3) * STAGE_BYTES;
        const uint32_t s1 = smem_base + (uint32_t)((c + 1) & 3) * STAGE_BYTES;

        load_frags0(s0, s0 + A_STAGE_BYTES);    // post-barrier: safe
        compute_stage(s0, s0 + A_STAGE_BYTES);
        load_frags0(s1, s1 + A_STAGE_BYTES);    // overlaps s0's tail MMAs
        compute_stage(s1, s1 + A_STAGE_BYTES);
    }

    // epilogue: y * 2^s_exp + bias from smem-staged constants
    const float* scs = reinterpret_cast<const float*>(smem + STAGES * STAGE_BYTES);
    const float* bis = scs + 256;
    const int col_lo = 2 * (lane & 3);
    const int row_lo = lane >> 2;
#pragma unroll
    for (int j = 0; j < 8; ++j) {
        const int ncl = wn * 64 + j * 8 + col_lo;       // 0..255 local column
        const int nc  = n0 + ncl;
        const float s0 = scs[ncl], s1 = scs[ncl + 1];
        const float b0 = bis[ncl], b1 = bis[ncl + 1];
#pragma unroll
        for (int i = 0; i < 2; ++i) {
            const int mr = m0 + wm * 32 + i * 16 + row_lo;
            float2 v0, v1;
            v0.x = acc[i][j][0] * s0 + b0;  v0.y = acc[i][j][1] * s1 + b1;
            v1.x = acc[i][j][2] * s0 + b0;  v1.y = acc[i][j][3] * s1 + b1;
            __stcs(reinterpret_cast<float2*>(out + (size_t)mr * N_TOTAL + nc), v0);
            __stcs(reinterpret_cast<float2*>(out + (size_t)(mr + 8) * N_TOTAL + nc), v1);
        }
    }
}

// ---------------------------------------------------------------------------
// host launcher — bind by element count; 2 launches per call
// ---------------------------------------------------------------------------
extern "C" void kernel_launch(void* const* d_in, const int* in_sizes, int n_in,
                              void* d_out, int out_size) {
    const void* x_p  = nullptr;
    const void* w_p  = nullptr;
    const void* c0_p = nullptr;
    const void* c1_p = nullptr;
    for (int i = 0; i < n_in; ++i) {
        if      (in_sizes[i] == M_TOTAL * K_TOTAL) x_p = d_in[i];
        else if (in_sizes[i] == N_TOTAL * K_TOTAL) w_p = d_in[i];
        else if (!c0_p)                            c0_p = d_in[i];
        else                                       c1_p = d_in[i];
    }
    float* out = (float*)d_out;

    static bool attr_set = false;
    if (!attr_set) {
        cudaFuncSetAttribute(bitlinear_gemm_kernel,
                             cudaFuncAttributeMaxDynamicSharedMemorySize, SMEM_TOTAL);
        attr_set = true;
    }

    prep_cvt_kernel<<<1 + XBLK + WBLK, 512>>>((const float*)x_p, w_p, c0_p, c1_p);

    dim3 grid(N_TOTAL / BN, M_TOTAL / BM);   // (8, 128), n fastest
    bitlinear_gemm_kernel<<<grid, THREADS, SMEM_TOTAL>>>(out);
}